// round 1
// baseline (speedup 1.0000x reference)
#include <cuda_runtime.h>
#include <cstdint>

// Problem constants (B=16, T=2048, D=512, K=4096)
#define N_ROWS 32768
#define DDIM   512
#define KCODES 4096

// Block-tile config for fused GEMM+argmin
#define BM 128   // rows per block
#define BN 128   // codes per chunk
#define BK 16    // D-tile depth
#define TM 8     // microtile rows per thread
#define TN 8     // microtile cols per thread
// 16x16 threads = 256

// Scratch (no cudaMalloc allowed)
__device__ float g_cnorm[KCODES];
__device__ int   g_nearest[N_ROWS];

// ---------------------------------------------------------------------------
// Kernel 1: codebook squared norms. 4096 blocks x 128 threads.
// ---------------------------------------------------------------------------
__global__ void cnorm_kernel(const float* __restrict__ cb) {
    int k = blockIdx.x;
    const float4* row = reinterpret_cast<const float4*>(cb + (size_t)k * DDIM);
    float s = 0.f;
    for (int i = threadIdx.x; i < DDIM / 4; i += 128) {
        float4 v = row[i];
        s += v.x * v.x + v.y * v.y + v.z * v.z + v.w * v.w;
    }
#pragma unroll
    for (int o = 16; o > 0; o >>= 1) s += __shfl_xor_sync(0xffffffffu, s, o);
    __shared__ float ws[4];
    if ((threadIdx.x & 31) == 0) ws[threadIdx.x >> 5] = s;
    __syncthreads();
    if (threadIdx.x == 0) g_cnorm[k] = ws[0] + ws[1] + ws[2] + ws[3];
}

// ---------------------------------------------------------------------------
// Kernel 2: fused GEMM + running argmin.
// Each block owns 128 input rows; loops over 32 chunks of 128 codes.
// For each chunk: full-D (512) register-blocked fp32 GEMM, then update the
// per-row running (min d2, argmin).
// ---------------------------------------------------------------------------
__global__ void __launch_bounds__(256, 2)
vq_argmin_kernel(const float* __restrict__ inp, const float* __restrict__ cb) {
    __shared__ float As[BK][BM];   // 8 KB  (transposed: [d][row])
    __shared__ float Bs[BK][BN];   // 8 KB  (transposed: [d][code])

    const int tid = threadIdx.x;
    const int tx = tid & 15;       // code-group 0..15
    const int ty = tid >> 4;       // row-group  0..15
    const int r0 = blockIdx.x * BM;

    float best_val[TM];
    int   best_idx[TM];
#pragma unroll
    for (int i = 0; i < TM; ++i) { best_val[i] = 3.0e38f; best_idx[i] = 0; }

    for (int c0 = 0; c0 < KCODES; c0 += BN) {
        float acc[TM][TN];
#pragma unroll
        for (int i = 0; i < TM; ++i)
#pragma unroll
            for (int j = 0; j < TN; ++j) acc[i][j] = 0.f;

        for (int kk = 0; kk < DDIM; kk += BK) {
            // Cooperative loads: 128 rows x 16 cols per tile = 512 float4s.
            // idx -> (row = idx/4, c4 = idx%4); global reads are 16B chunks,
            // 4 consecutive per row (64B runs) — acceptable, all L2-resident.
#pragma unroll
            for (int p = 0; p < 2; ++p) {
                int idx = tid + p * 256;
                int row = idx >> 2;
                int c4  = idx & 3;
                float4 va = *reinterpret_cast<const float4*>(
                    inp + (size_t)(r0 + row) * DDIM + kk + c4 * 4);
                float4 vb = *reinterpret_cast<const float4*>(
                    cb + (size_t)(c0 + row) * DDIM + kk + c4 * 4);
                As[c4 * 4 + 0][row] = va.x;
                As[c4 * 4 + 1][row] = va.y;
                As[c4 * 4 + 2][row] = va.z;
                As[c4 * 4 + 3][row] = va.w;
                Bs[c4 * 4 + 0][row] = vb.x;
                Bs[c4 * 4 + 1][row] = vb.y;
                Bs[c4 * 4 + 2][row] = vb.z;
                Bs[c4 * 4 + 3][row] = vb.w;
            }
            __syncthreads();

#pragma unroll
            for (int t = 0; t < BK; ++t) {
                float4 a0 = *reinterpret_cast<const float4*>(&As[t][ty * TM]);
                float4 a1 = *reinterpret_cast<const float4*>(&As[t][ty * TM + 4]);
                float4 b0 = *reinterpret_cast<const float4*>(&Bs[t][tx * TN]);
                float4 b1 = *reinterpret_cast<const float4*>(&Bs[t][tx * TN + 4]);
                float a[TM] = {a0.x, a0.y, a0.z, a0.w, a1.x, a1.y, a1.z, a1.w};
                float b[TN] = {b0.x, b0.y, b0.z, b0.w, b1.x, b1.y, b1.z, b1.w};
#pragma unroll
                for (int i = 0; i < TM; ++i)
#pragma unroll
                    for (int j = 0; j < TN; ++j)
                        acc[i][j] = fmaf(a[i], b[j], acc[i][j]);
            }
            __syncthreads();
        }

        // d2 = ||c||^2 - 2*x.c ; running min (strict < keeps first occurrence
        // in ascending-index order within this thread's candidates)
#pragma unroll
        for (int j = 0; j < TN; ++j) {
            int cidx = c0 + tx * TN + j;
            float cn = __ldg(&g_cnorm[cidx]);
#pragma unroll
            for (int i = 0; i < TM; ++i) {
                float d2 = fmaf(-2.f, acc[i][j], cn);
                if (d2 < best_val[i]) { best_val[i] = d2; best_idx[i] = cidx; }
            }
        }
    }

    // Cross-thread (tx) reduction per row, reusing tile smem.
    __syncthreads();
    float (*redv)[16] = reinterpret_cast<float(*)[16]>(&As[0][0]);  // [128][16]
    int   (*redi)[16] = reinterpret_cast<int  (*)[16]>(&Bs[0][0]);  // [128][16]
#pragma unroll
    for (int i = 0; i < TM; ++i) {
        redv[ty * TM + i][tx] = best_val[i];
        redi[ty * TM + i][tx] = best_idx[i];
    }
    __syncthreads();
    if (tid < BM) {
        float bv = redv[tid][0];
        int   bi = redi[tid][0];
#pragma unroll
        for (int t = 1; t < 16; ++t) {
            float v = redv[tid][t];
            int   d = redi[tid][t];
            if (v < bv || (v == bv && d < bi)) { bv = v; bi = d; }
        }
        g_nearest[r0 + tid] = bi;
    }
}

// ---------------------------------------------------------------------------
// Kernel 3: gather codebook rows into output. One block (128 threads) per row.
// ---------------------------------------------------------------------------
__global__ void gather_kernel(const float* __restrict__ cb, float* __restrict__ out) {
    int n = blockIdx.x;
    int k = g_nearest[n];
    const float4* src = reinterpret_cast<const float4*>(cb + (size_t)k * DDIM);
    float4* dst = reinterpret_cast<float4*>(out + (size_t)n * DDIM);
    dst[threadIdx.x] = src[threadIdx.x];
}

// ---------------------------------------------------------------------------
extern "C" void kernel_launch(void* const* d_in, const int* in_sizes, int n_in,
                              void* d_out, int out_size) {
    const float* inputs   = (const float*)d_in[0];  // [16,2048,512]
    const float* codebook = (const float*)d_in[1];  // [4096,512]
    float* out = (float*)d_out;                     // [16,2048,512]

    cnorm_kernel<<<KCODES, 128>>>(codebook);
    vq_argmin_kernel<<<N_ROWS / BM, 256>>>(inputs, codebook);
    gather_kernel<<<N_ROWS, 128>>>(codebook, out);
}

// round 3
// speedup vs baseline: 2.4341x; 2.4341x over previous
#include <cuda_runtime.h>
#include <cuda_bf16.h>
#include <cstdint>

// Problem constants
#define N_ROWS 32768
#define DDIM   512
#define KCODES 4096

// Tiling
#define MT 128                 // rows per CTA
#define NT 128                 // codes per chunk
#define BK 64                  // K per SMEM tile (64 bf16 = 128B rows, SW128)
#define NCHUNKS (KCODES / NT)  // 32
#define KTILES_PER_CHUNK 24    // 1536 / 64  (3-way split of D=512)
#define TOTAL_TILES (NCHUNKS * KTILES_PER_CHUNK)  // 768
#define NSTG 3

#define STAGE_BYTES 32768      // A 16KB + B 16KB
#define SMEM_TOTAL (NSTG * STAGE_BYTES)  // 98304

// ---------------- scratch ----------------
__device__ __nv_bfloat16 g_Ah[(size_t)N_ROWS * DDIM];
__device__ __nv_bfloat16 g_Al[(size_t)N_ROWS * DDIM];
__device__ __nv_bfloat16 g_Ch[(size_t)KCODES * DDIM];
__device__ __nv_bfloat16 g_Cl[(size_t)KCODES * DDIM];
__device__ float g_cnorm[KCODES];
__device__ int   g_nearest[N_ROWS];

// ---------------- PTX helpers (all plain sm_80-era, legal on compute_103) ----
__device__ __forceinline__ uint32_t smem_to_u32(const void* p) {
    uint32_t a;
    asm("{ .reg .u64 t; cvta.to.shared.u64 t, %1; cvt.u32.u64 %0, t; }" : "=r"(a) : "l"(p));
    return a;
}
__device__ __forceinline__ void cp_async16(uint32_t dst, const void* src) {
    asm volatile("cp.async.cg.shared.global [%0], [%1], 16;" :: "r"(dst), "l"(src) : "memory");
}
#define CP_COMMIT() asm volatile("cp.async.commit_group;" ::: "memory")
#define CP_WAIT(n)  asm volatile("cp.async.wait_group %0;" :: "n"(n) : "memory")

__device__ __forceinline__ void ldsm_x4(uint32_t& r0, uint32_t& r1, uint32_t& r2,
                                        uint32_t& r3, uint32_t addr) {
    asm volatile("ldmatrix.sync.aligned.m8n8.x4.shared.b16 {%0,%1,%2,%3}, [%4];"
                 : "=r"(r0), "=r"(r1), "=r"(r2), "=r"(r3) : "r"(addr));
}
__device__ __forceinline__ void mma16816(float* d, const uint32_t* a,
                                         uint32_t b0, uint32_t b1) {
    asm volatile(
        "mma.sync.aligned.m16n8k16.row.col.f32.bf16.bf16.f32 "
        "{%0,%1,%2,%3}, {%4,%5,%6,%7}, {%8,%9}, {%0,%1,%2,%3};"
        : "+f"(d[0]), "+f"(d[1]), "+f"(d[2]), "+f"(d[3])
        : "r"(a[0]), "r"(a[1]), "r"(a[2]), "r"(a[3]), "r"(b0), "r"(b1));
}
// SW128 swizzle: 128B rows, XOR 16B-chunk index with (row & 7)
__device__ __forceinline__ uint32_t sw_off(int row, int chunk) {
    return (uint32_t)(row * 128 + ((chunk ^ (row & 7)) << 4));
}

// ---------------------------------------------------------------------------
// Precompute: fp32 -> (bf16 hi, bf16 residual)
// ---------------------------------------------------------------------------
__global__ void split_inputs_kernel(const float* __restrict__ src) {
    int n4 = N_ROWS * DDIM / 4;
    for (int i = blockIdx.x * blockDim.x + threadIdx.x; i < n4; i += gridDim.x * blockDim.x) {
        float4 v = reinterpret_cast<const float4*>(src)[i];
        float f[4] = {v.x, v.y, v.z, v.w};
        __nv_bfloat16 h[4], l[4];
#pragma unroll
        for (int j = 0; j < 4; ++j) {
            h[j] = __float2bfloat16_rn(f[j]);
            l[j] = __float2bfloat16_rn(f[j] - __bfloat162float(h[j]));
        }
        reinterpret_cast<uint2*>(g_Ah)[i] = *reinterpret_cast<uint2*>(h);
        reinterpret_cast<uint2*>(g_Al)[i] = *reinterpret_cast<uint2*>(l);
    }
}
__global__ void split_codebook_kernel(const float* __restrict__ src) {
    int n4 = KCODES * DDIM / 4;
    for (int i = blockIdx.x * blockDim.x + threadIdx.x; i < n4; i += gridDim.x * blockDim.x) {
        float4 v = reinterpret_cast<const float4*>(src)[i];
        float f[4] = {v.x, v.y, v.z, v.w};
        __nv_bfloat16 h[4], l[4];
#pragma unroll
        for (int j = 0; j < 4; ++j) {
            h[j] = __float2bfloat16_rn(f[j]);
            l[j] = __float2bfloat16_rn(f[j] - __bfloat162float(h[j]));
        }
        reinterpret_cast<uint2*>(g_Ch)[i] = *reinterpret_cast<uint2*>(h);
        reinterpret_cast<uint2*>(g_Cl)[i] = *reinterpret_cast<uint2*>(l);
    }
}
__global__ void cnorm_kernel(const float* __restrict__ cb) {
    int k = blockIdx.x;
    const float4* row = reinterpret_cast<const float4*>(cb + (size_t)k * DDIM);
    float s = 0.f;
    for (int i = threadIdx.x; i < DDIM / 4; i += 128) {
        float4 v = row[i];
        s += v.x * v.x + v.y * v.y + v.z * v.z + v.w * v.w;
    }
#pragma unroll
    for (int o = 16; o > 0; o >>= 1) s += __shfl_xor_sync(0xffffffffu, s, o);
    __shared__ float ws[4];
    if ((threadIdx.x & 31) == 0) ws[threadIdx.x >> 5] = s;
    __syncthreads();
    if (threadIdx.x == 0) g_cnorm[k] = ws[0] + ws[1] + ws[2] + ws[3];
}

// ---------------------------------------------------------------------------
// Fused HMMA GEMM + argmin. Grid 256 x 256 threads (8 warps, 2x4 warp grid).
// ---------------------------------------------------------------------------
__device__ __forceinline__ void issue_stage_loads(
    uint32_t aBase, uint32_t bBase,
    const __nv_bfloat16* __restrict__ srcA, const __nv_bfloat16* __restrict__ srcB,
    int r0, int c0, int ks, int tid) {
#pragma unroll
    for (int i = 0; i < 4; ++i) {
        int idx = tid + i * 256;        // 0..1023
        int row = idx >> 3, ch = idx & 7;
        cp_async16(aBase + sw_off(row, ch),
                   srcA + (size_t)(r0 + row) * DDIM + ks + ch * 8);
    }
#pragma unroll
    for (int i = 0; i < 4; ++i) {
        int idx = tid + i * 256;
        int row = idx >> 3, ch = idx & 7;
        cp_async16(bBase + sw_off(row, ch),
                   srcB + (size_t)(c0 + row) * DDIM + ks + ch * 8);
    }
    CP_COMMIT();
}

__global__ void __launch_bounds__(256, 1)
vq_hmma_kernel() {
    extern __shared__ char smem[];
    const uint32_t sb = smem_to_u32(smem);
    const int tid  = threadIdx.x;
    const int lane = tid & 31;
    const int warp = tid >> 5;
    const int wm = warp >> 2;          // 0..1  (64 rows each)
    const int wn = warp & 3;           // 0..3  (32 codes each)
    const int r0 = blockIdx.x * MT;

    const int sub   = lane >> 3;
    const int lrow  = (sub & 1) * 8 + (lane & 7);  // row within 16-row tile
    const int lchk  = sub >> 1;                    // 0/1: which 16B k-chunk

    float acc[4][4][4];
#pragma unroll
    for (int mi = 0; mi < 4; ++mi)
#pragma unroll
        for (int n8 = 0; n8 < 4; ++n8)
#pragma unroll
            for (int e = 0; e < 4; ++e) acc[mi][n8][e] = 0.f;

    float best_val[8];
    int   best_idx[8];
#pragma unroll
    for (int b = 0; b < 8; ++b) { best_val[b] = 3.0e38f; best_idx[b] = 0; }

    // Prologue: stages 0 and 1 = tiles (chunk0, kt0) and (chunk0, kt1)
    issue_stage_loads(sb + 0 * STAGE_BYTES, sb + 0 * STAGE_BYTES + 16384,
                      g_Ah, g_Ch, r0, 0, 0, tid);
    issue_stage_loads(sb + 1 * STAGE_BYTES, sb + 1 * STAGE_BYTES + 16384,
                      g_Ah, g_Ch, r0, 0, 64, tid);

    int t = 0;
#pragma unroll 1
    for (int chunk = 0; chunk < NCHUNKS; ++chunk) {
        const int c0 = chunk * NT;
#pragma unroll 1
        for (int kt = 0; kt < KTILES_PER_CHUNK; ++kt, ++t) {
            // Wait for tile t's data
            if (t == TOTAL_TILES - 1) { CP_WAIT(0); } else { CP_WAIT(1); }
            __syncthreads();

            // Issue loads for tile t+2 into stage (t+2)%3 (freed at iter t-1)
            if (t + 2 < TOTAL_TILES) {
                int ktL = kt + 2, chL = chunk;
                if (ktL >= KTILES_PER_CHUNK) { ktL -= KTILES_PER_CHUNK; ++chL; }
                const int region = ktL >> 3;
                const int ks = (ktL & 7) * 64;
                const __nv_bfloat16* srcA = (region == 1) ? g_Al : g_Ah;
                const __nv_bfloat16* srcB = (region == 2) ? g_Cl : g_Ch;
                const int s2 = (t + 2) % NSTG;
                issue_stage_loads(sb + s2 * STAGE_BYTES, sb + s2 * STAGE_BYTES + 16384,
                                  srcA, srcB, r0, chL * NT, ks, tid);
            }

            // Compute on stage t%3
            const uint32_t aBase = sb + (t % NSTG) * STAGE_BYTES;
            const uint32_t bBase = aBase + 16384;
#pragma unroll
            for (int kk = 0; kk < 4; ++kk) {
                uint32_t a[4][4];
#pragma unroll
                for (int mi = 0; mi < 4; ++mi)
                    ldsm_x4(a[mi][0], a[mi][1], a[mi][2], a[mi][3],
                            aBase + sw_off(wm * 64 + mi * 16 + lrow, kk * 2 + lchk));
                uint32_t bfr[2][4];
#pragma unroll
                for (int ni2 = 0; ni2 < 2; ++ni2)
                    ldsm_x4(bfr[ni2][0], bfr[ni2][1], bfr[ni2][2], bfr[ni2][3],
                            bBase + sw_off(wn * 32 + ni2 * 16 + lrow, kk * 2 + lchk));
#pragma unroll
                for (int mi = 0; mi < 4; ++mi)
#pragma unroll
                    for (int n8 = 0; n8 < 4; ++n8)
                        mma16816(acc[mi][n8], a[mi],
                                 bfr[n8 >> 1][n8 & 1], bfr[n8 >> 1][(n8 & 1) + 2]);
            }

            // End of chunk: fold accumulators into the running argmin
            if (kt == KTILES_PER_CHUNK - 1) {
#pragma unroll
                for (int n8 = 0; n8 < 4; ++n8) {
                    const int col = c0 + wn * 32 + n8 * 8 + 2 * (lane & 3);
                    const float cn0 = __ldg(&g_cnorm[col]);
                    const float cn1 = __ldg(&g_cnorm[col + 1]);
#pragma unroll
                    for (int mi = 0; mi < 4; ++mi) {
                        float d0 = fmaf(-2.f, acc[mi][n8][0], cn0);
                        float d1 = fmaf(-2.f, acc[mi][n8][1], cn1);
                        float d2 = fmaf(-2.f, acc[mi][n8][2], cn0);
                        float d3 = fmaf(-2.f, acc[mi][n8][3], cn1);
                        const int blo = mi * 2, bhi = mi * 2 + 1;
                        if (d0 < best_val[blo]) { best_val[blo] = d0; best_idx[blo] = col; }
                        if (d1 < best_val[blo]) { best_val[blo] = d1; best_idx[blo] = col + 1; }
                        if (d2 < best_val[bhi]) { best_val[bhi] = d2; best_idx[bhi] = col; }
                        if (d3 < best_val[bhi]) { best_val[bhi] = d3; best_idx[bhi] = col + 1; }
                        acc[mi][n8][0] = 0.f; acc[mi][n8][1] = 0.f;
                        acc[mi][n8][2] = 0.f; acc[mi][n8][3] = 0.f;
                    }
                }
            }
        }
    }

    // Final cross-thread reduction (reuse stage-0 smem)
    __syncthreads();
    float* redv = reinterpret_cast<float*>(smem);          // [128][4]
    int*   redi = reinterpret_cast<int*>(smem + 2048);     // [128][4]
#pragma unroll
    for (int b = 0; b < 8; ++b) {
        float v = best_val[b];
        int   ix = best_idx[b];
#pragma unroll
        for (int off = 1; off <= 2; off <<= 1) {
            float ov = __shfl_xor_sync(0xffffffffu, v, off);
            int   oi = __shfl_xor_sync(0xffffffffu, ix, off);
            if (ov < v || (ov == v && oi < ix)) { v = ov; ix = oi; }
        }
        if ((lane & 3) == 0) {
            int row = wm * 64 + (b >> 1) * 16 + (b & 1) * 8 + (lane >> 2);
            redv[row * 4 + wn] = v;
            redi[row * 4 + wn] = ix;
        }
    }
    __syncthreads();
    if (tid < MT) {
        float bv = redv[tid * 4 + 0];
        int   bi = redi[tid * 4 + 0];
#pragma unroll
        for (int w = 1; w < 4; ++w) {
            float v = redv[tid * 4 + w];
            int   ix = redi[tid * 4 + w];
            if (v < bv || (v == bv && ix < bi)) { bv = v; bi = ix; }
        }
        g_nearest[r0 + tid] = bi;
    }
}

// ---------------------------------------------------------------------------
// Gather + exact STE rounding: out = (q - x) + x  (matches reference fp32 ops)
// ---------------------------------------------------------------------------
__global__ void gather_kernel(const float* __restrict__ cb, const float* __restrict__ x,
                              float* __restrict__ out) {
    int n = blockIdx.x;
    int k = g_nearest[n];
    float4 qv = reinterpret_cast<const float4*>(cb + (size_t)k * DDIM)[threadIdx.x];
    float4 xv = reinterpret_cast<const float4*>(x + (size_t)n * DDIM)[threadIdx.x];
    float4 r;
    r.x = (qv.x - xv.x) + xv.x;
    r.y = (qv.y - xv.y) + xv.y;
    r.z = (qv.z - xv.z) + xv.z;
    r.w = (qv.w - xv.w) + xv.w;
    reinterpret_cast<float4*>(out + (size_t)n * DDIM)[threadIdx.x] = r;
}

// ---------------------------------------------------------------------------
extern "C" void kernel_launch(void* const* d_in, const int* in_sizes, int n_in,
                              void* d_out, int out_size) {
    const float* inputs   = (const float*)d_in[0];
    const float* codebook = (const float*)d_in[1];
    float* out = (float*)d_out;

    cudaFuncSetAttribute(vq_hmma_kernel, cudaFuncAttributeMaxDynamicSharedMemorySize,
                         SMEM_TOTAL);

    split_inputs_kernel<<<4096, 256>>>(inputs);
    split_codebook_kernel<<<512, 256>>>(codebook);
    cnorm_kernel<<<KCODES, 128>>>(codebook);
    vq_hmma_kernel<<<N_ROWS / MT, 256, SMEM_TOTAL>>>();
    gather_kernel<<<N_ROWS, 128>>>(codebook, inputs, out);
}

// round 4
// speedup vs baseline: 6.0533x; 2.4869x over previous
#include <cuda_runtime.h>
#include <cuda_bf16.h>
#include <cstdint>

// Problem constants
#define N_ROWS 32768
#define DDIM   512
#define KCODES 4096

// Tiling (coarse pass)
#define MT 128                 // rows per CTA
#define NT 128                 // codes per chunk
#define BK 64                  // K per SMEM tile
#define NCHUNKS (KCODES / NT)          // 32
#define KT_PER_CHUNK (DDIM / BK)       // 8
#define TOTAL_TILES (NCHUNKS * KT_PER_CHUNK)  // 256
#define NSTG 3
#define STAGE_BYTES 32768      // A 16KB + B 16KB
#define SMEM_TOTAL (NSTG * STAGE_BYTES)

// ---------------- scratch ----------------
__device__ __nv_bfloat16 g_Ah[(size_t)N_ROWS * DDIM];
__device__ __nv_bfloat16 g_Ch[(size_t)KCODES * DDIM];
__device__ float g_cnorm[KCODES];
__device__ int   g_cand[N_ROWS * 4];

// ---------------- PTX helpers ----------------
__device__ __forceinline__ uint32_t smem_to_u32(const void* p) {
    uint32_t a;
    asm("{ .reg .u64 t; cvta.to.shared.u64 t, %1; cvt.u32.u64 %0, t; }" : "=r"(a) : "l"(p));
    return a;
}
__device__ __forceinline__ void cp_async16(uint32_t dst, const void* src) {
    asm volatile("cp.async.cg.shared.global [%0], [%1], 16;" :: "r"(dst), "l"(src) : "memory");
}
#define CP_COMMIT() asm volatile("cp.async.commit_group;" ::: "memory")
#define CP_WAIT(n)  asm volatile("cp.async.wait_group %0;" :: "n"(n) : "memory")

__device__ __forceinline__ void ldsm_x4(uint32_t& r0, uint32_t& r1, uint32_t& r2,
                                        uint32_t& r3, uint32_t addr) {
    asm volatile("ldmatrix.sync.aligned.m8n8.x4.shared.b16 {%0,%1,%2,%3}, [%4];"
                 : "=r"(r0), "=r"(r1), "=r"(r2), "=r"(r3) : "r"(addr));
}
__device__ __forceinline__ void mma16816(float* d, const uint32_t* a,
                                         uint32_t b0, uint32_t b1) {
    asm volatile(
        "mma.sync.aligned.m16n8k16.row.col.f32.bf16.bf16.f32 "
        "{%0,%1,%2,%3}, {%4,%5,%6,%7}, {%8,%9}, {%0,%1,%2,%3};"
        : "+f"(d[0]), "+f"(d[1]), "+f"(d[2]), "+f"(d[3])
        : "r"(a[0]), "r"(a[1]), "r"(a[2]), "r"(a[3]), "r"(b0), "r"(b1));
}
__device__ __forceinline__ uint32_t sw_off(int row, int chunk) {
    return (uint32_t)(row * 128 + ((chunk ^ (row & 7)) << 4));
}

// ---------------------------------------------------------------------------
// Precompute kernels
// ---------------------------------------------------------------------------
__global__ void split_inputs_kernel(const float* __restrict__ src) {
    int n4 = N_ROWS * DDIM / 4;
    for (int i = blockIdx.x * blockDim.x + threadIdx.x; i < n4; i += gridDim.x * blockDim.x) {
        float4 v = reinterpret_cast<const float4*>(src)[i];
        __nv_bfloat16 h[4] = {__float2bfloat16_rn(v.x), __float2bfloat16_rn(v.y),
                              __float2bfloat16_rn(v.z), __float2bfloat16_rn(v.w)};
        reinterpret_cast<uint2*>(g_Ah)[i] = *reinterpret_cast<uint2*>(h);
    }
}
__global__ void split_codebook_kernel(const float* __restrict__ src) {
    int n4 = KCODES * DDIM / 4;
    for (int i = blockIdx.x * blockDim.x + threadIdx.x; i < n4; i += gridDim.x * blockDim.x) {
        float4 v = reinterpret_cast<const float4*>(src)[i];
        __nv_bfloat16 h[4] = {__float2bfloat16_rn(v.x), __float2bfloat16_rn(v.y),
                              __float2bfloat16_rn(v.z), __float2bfloat16_rn(v.w)};
        reinterpret_cast<uint2*>(g_Ch)[i] = *reinterpret_cast<uint2*>(h);
    }
}
__global__ void cnorm_kernel(const float* __restrict__ cb) {
    int k = blockIdx.x;
    const float4* row = reinterpret_cast<const float4*>(cb + (size_t)k * DDIM);
    float s = 0.f;
    for (int i = threadIdx.x; i < DDIM / 4; i += 128) {
        float4 v = row[i];
        s += v.x * v.x + v.y * v.y + v.z * v.z + v.w * v.w;
    }
#pragma unroll
    for (int o = 16; o > 0; o >>= 1) s += __shfl_xor_sync(0xffffffffu, s, o);
    __shared__ float ws[4];
    if ((threadIdx.x & 31) == 0) ws[threadIdx.x >> 5] = s;
    __syncthreads();
    if (threadIdx.x == 0) g_cnorm[k] = ws[0] + ws[1] + ws[2] + ws[3];
}

// ---------------------------------------------------------------------------
// Coarse pass: bf16 GEMM (xh . ch) + per-thread top-2 per row-slot,
// merged to global top-4 candidates per row.
// Grid 256 CTAs x 512 threads (16 warps, 4x4 warp grid, warp tile 32x32).
// ---------------------------------------------------------------------------
__device__ __forceinline__ void issue_stage(uint32_t aBase, uint32_t bBase,
                                            int r0, int c0, int ks, int tid) {
#pragma unroll
    for (int i = 0; i < 2; ++i) {
        int idx = tid + i * 512;        // 0..1023
        int row = idx >> 3, ch = idx & 7;
        cp_async16(aBase + sw_off(row, ch),
                   g_Ah + (size_t)(r0 + row) * DDIM + ks + ch * 8);
    }
#pragma unroll
    for (int i = 0; i < 2; ++i) {
        int idx = tid + i * 512;
        int row = idx >> 3, ch = idx & 7;
        cp_async16(bBase + sw_off(row, ch),
                   g_Ch + (size_t)(c0 + row) * DDIM + ks + ch * 8);
    }
    CP_COMMIT();
}

__global__ void __launch_bounds__(512, 1)
vq_coarse_kernel() {
    extern __shared__ char smem[];
    const uint32_t sb = smem_to_u32(smem);
    const int tid  = threadIdx.x;
    const int lane = tid & 31;
    const int warp = tid >> 5;
    const int wm = warp >> 2;          // 0..3 (32 rows each)
    const int wn = warp & 3;           // 0..3 (32 codes each)
    const int r0 = blockIdx.x * MT;

    const int sub  = lane >> 3;
    const int lrow = (sub & 1) * 8 + (lane & 7);
    const int lchk = sub >> 1;

    float acc[2][4][4];
#pragma unroll
    for (int mi = 0; mi < 2; ++mi)
#pragma unroll
        for (int n8 = 0; n8 < 4; ++n8)
#pragma unroll
            for (int e = 0; e < 4; ++e) acc[mi][n8][e] = 0.f;

    // per row-slot top-2 (4 slots: mi*2 + rowhalf)
    float v0[4], v1[4];
    int   i0[4], i1[4];
#pragma unroll
    for (int s = 0; s < 4; ++s) { v0[s] = v1[s] = 3.0e38f; i0[s] = i1[s] = 0x7fffffff; }

    issue_stage(sb, sb + 16384, r0, 0, 0, tid);
    issue_stage(sb + STAGE_BYTES, sb + STAGE_BYTES + 16384, r0, 0, 64, tid);

#pragma unroll 1
    for (int t = 0; t < TOTAL_TILES; ++t) {
        const int chunk = t >> 3;
        const int kt = t & 7;

        if (t == TOTAL_TILES - 1) { CP_WAIT(0); } else { CP_WAIT(1); }
        __syncthreads();

        if (t + 2 < TOTAL_TILES) {
            const int t2 = t + 2;
            const int s2 = t2 % NSTG;
            issue_stage(sb + s2 * STAGE_BYTES, sb + s2 * STAGE_BYTES + 16384,
                        r0, (t2 >> 3) * NT, (t2 & 7) * BK, tid);
        }

        const uint32_t aBase = sb + (t % NSTG) * STAGE_BYTES;
        const uint32_t bBase = aBase + 16384;
#pragma unroll
        for (int kk = 0; kk < 4; ++kk) {
            uint32_t a[2][4];
#pragma unroll
            for (int mi = 0; mi < 2; ++mi)
                ldsm_x4(a[mi][0], a[mi][1], a[mi][2], a[mi][3],
                        aBase + sw_off(wm * 32 + mi * 16 + lrow, kk * 2 + lchk));
            uint32_t bfr[2][4];
#pragma unroll
            for (int ni = 0; ni < 2; ++ni)
                ldsm_x4(bfr[ni][0], bfr[ni][1], bfr[ni][2], bfr[ni][3],
                        bBase + sw_off(wn * 32 + ni * 16 + lrow, kk * 2 + lchk));
#pragma unroll
            for (int mi = 0; mi < 2; ++mi)
#pragma unroll
                for (int n8 = 0; n8 < 4; ++n8)
                    mma16816(acc[mi][n8], a[mi],
                             bfr[n8 >> 1][n8 & 1], bfr[n8 >> 1][(n8 & 1) + 2]);
        }

        if (kt == KT_PER_CHUNK - 1) {
            const int c0 = chunk * NT;
#pragma unroll
            for (int n8 = 0; n8 < 4; ++n8) {
                const int col = c0 + wn * 32 + n8 * 8 + 2 * (lane & 3);
                const float cn0 = __ldg(&g_cnorm[col]);
                const float cn1 = __ldg(&g_cnorm[col + 1]);
#pragma unroll
                for (int mi = 0; mi < 2; ++mi) {
#pragma unroll
                    for (int e = 0; e < 4; ++e) {
                        const int slot = mi * 2 + (e >> 1);
                        const float cn = (e & 1) ? cn1 : cn0;
                        const int   cx = col + (e & 1);
                        float d = fmaf(-2.f, acc[mi][n8][e], cn);
                        if (d < v1[slot]) {
                            if (d < v0[slot]) {
                                v1[slot] = v0[slot]; i1[slot] = i0[slot];
                                v0[slot] = d;        i0[slot] = cx;
                            } else { v1[slot] = d; i1[slot] = cx; }
                        }
                        acc[mi][n8][e] = 0.f;
                    }
                }
            }
        }
    }

    // Merge 16 threads x 2 entries per row -> global top-4 per row
    __syncthreads();
    float* mv = reinterpret_cast<float*>(smem);            // [128][32]
    int*   md = reinterpret_cast<int*>(smem + 16384);      // [128][32]
#pragma unroll
    for (int slot = 0; slot < 4; ++slot) {
        const int mi = slot >> 1, rh = slot & 1;
        const int row = wm * 32 + mi * 16 + rh * 8 + (lane >> 2);
        const int col = wn * 8 + (lane & 3) * 2;
        mv[row * 32 + col]     = v0[slot];
        md[row * 32 + col]     = i0[slot];
        mv[row * 32 + col + 1] = v1[slot];
        md[row * 32 + col + 1] = i1[slot];
    }
    __syncthreads();
    if (tid < MT) {
        float tv[4] = {3.0e38f, 3.0e38f, 3.0e38f, 3.0e38f};
        int   ti[4] = {0x7fffffff, 0x7fffffff, 0x7fffffff, 0x7fffffff};
#pragma unroll 4
        for (int e = 0; e < 32; ++e) {
            float v = mv[tid * 32 + e];
            int   d = md[tid * 32 + e];
            if (v < tv[3] || (v == tv[3] && d < ti[3])) {
                tv[3] = v; ti[3] = d;
#pragma unroll
                for (int j = 3; j >= 1; --j) {
                    if (tv[j] < tv[j-1] || (tv[j] == tv[j-1] && ti[j] < ti[j-1])) {
                        float fv = tv[j]; tv[j] = tv[j-1]; tv[j-1] = fv;
                        int   fi = ti[j]; ti[j] = ti[j-1]; ti[j-1] = fi;
                    }
                }
            }
        }
#pragma unroll
        for (int j = 0; j < 4; ++j) g_cand[(r0 + tid) * 4 + j] = ti[j];
    }
}

// ---------------------------------------------------------------------------
// Exact refine + gather. One warp per row; 4 candidates, fp32 dots.
// ---------------------------------------------------------------------------
__global__ void __launch_bounds__(256)
refine_kernel(const float* __restrict__ cb, const float* __restrict__ x,
              float* __restrict__ out) {
    const int n = blockIdx.x * 8 + (threadIdx.x >> 5);
    const int lane = threadIdx.x & 31;

    float xr[16];
#pragma unroll
    for (int j = 0; j < 16; ++j) xr[j] = x[(size_t)n * DDIM + j * 32 + lane];

    float bv = 3.0e38f;
    int   bi = 0x7fffffff;
#pragma unroll
    for (int c = 0; c < 4; ++c) {
        const int k = g_cand[n * 4 + c];
        const float* crow = cb + (size_t)k * DDIM;
        float s = 0.f;
#pragma unroll
        for (int j = 0; j < 16; ++j) s = fmaf(xr[j], __ldg(crow + j * 32 + lane), s);
#pragma unroll
        for (int o = 16; o > 0; o >>= 1) s += __shfl_xor_sync(0xffffffffu, s, o);
        float d2 = fmaf(-2.f, s, __ldg(&g_cnorm[k]));
        if (d2 < bv || (d2 == bv && k < bi)) { bv = d2; bi = k; }
    }

    const float* q = cb + (size_t)bi * DDIM;
#pragma unroll
    for (int j = 0; j < 16; ++j) {
        float qv = __ldg(q + j * 32 + lane);
        float xv = xr[j];
        out[(size_t)n * DDIM + j * 32 + lane] = (qv - xv) + xv;
    }
}

// ---------------------------------------------------------------------------
extern "C" void kernel_launch(void* const* d_in, const int* in_sizes, int n_in,
                              void* d_out, int out_size) {
    const float* inputs   = (const float*)d_in[0];
    const float* codebook = (const float*)d_in[1];
    float* out = (float*)d_out;

    cudaFuncSetAttribute(vq_coarse_kernel, cudaFuncAttributeMaxDynamicSharedMemorySize,
                         SMEM_TOTAL);

    split_inputs_kernel<<<4096, 256>>>(inputs);
    split_codebook_kernel<<<512, 256>>>(codebook);
    cnorm_kernel<<<KCODES, 128>>>(codebook);
    vq_coarse_kernel<<<N_ROWS / MT, 512, SMEM_TOTAL>>>();
    refine_kernel<<<N_ROWS / 8, 256>>>(codebook, inputs, out);
}

// round 5
// speedup vs baseline: 6.9816x; 1.1534x over previous
#include <cuda_runtime.h>
#include <cuda_bf16.h>
#include <cstdint>

// Problem constants
#define N_ROWS 32768
#define DDIM   512
#define KCODES 4096

// Tiling (coarse pass)
#define MT 128                 // rows per CTA
#define NT 128                 // codes per chunk
#define BK 64                  // K per SMEM tile
#define NCHUNKS (KCODES / NT)          // 32
#define KT_PER_CHUNK (DDIM / BK)       // 8
#define TOTAL_TILES (NCHUNKS * KT_PER_CHUNK)  // 256
#define NSTG 3
#define STAGE_BYTES 32768      // A 16KB + B 16KB
#define SMEM_TOTAL (NSTG * STAGE_BYTES)

// ---------------- scratch ----------------
__device__ __nv_bfloat16 g_Ah[(size_t)N_ROWS * DDIM];
__device__ __nv_bfloat16 g_Ch[(size_t)KCODES * DDIM];
__device__ float g_cnorm[KCODES];
__device__ int   g_cand[N_ROWS * 4];

// ---------------- PTX helpers ----------------
__device__ __forceinline__ uint32_t smem_to_u32(const void* p) {
    uint32_t a;
    asm("{ .reg .u64 t; cvta.to.shared.u64 t, %1; cvt.u32.u64 %0, t; }" : "=r"(a) : "l"(p));
    return a;
}
__device__ __forceinline__ void cp_async16(uint32_t dst, const void* src) {
    asm volatile("cp.async.cg.shared.global [%0], [%1], 16;" :: "r"(dst), "l"(src) : "memory");
}
#define CP_COMMIT() asm volatile("cp.async.commit_group;" ::: "memory")
#define CP_WAIT(n)  asm volatile("cp.async.wait_group %0;" :: "n"(n) : "memory")

__device__ __forceinline__ void ldsm_x4(uint32_t& r0, uint32_t& r1, uint32_t& r2,
                                        uint32_t& r3, uint32_t addr) {
    asm volatile("ldmatrix.sync.aligned.m8n8.x4.shared.b16 {%0,%1,%2,%3}, [%4];"
                 : "=r"(r0), "=r"(r1), "=r"(r2), "=r"(r3) : "r"(addr));
}
__device__ __forceinline__ void mma16816(float* d, const uint32_t* a,
                                         uint32_t b0, uint32_t b1) {
    asm volatile(
        "mma.sync.aligned.m16n8k16.row.col.f32.bf16.bf16.f32 "
        "{%0,%1,%2,%3}, {%4,%5,%6,%7}, {%8,%9}, {%0,%1,%2,%3};"
        : "+f"(d[0]), "+f"(d[1]), "+f"(d[2]), "+f"(d[3])
        : "r"(a[0]), "r"(a[1]), "r"(a[2]), "r"(a[3]), "r"(b0), "r"(b1));
}
__device__ __forceinline__ uint32_t sw_off(int row, int chunk) {
    return (uint32_t)(row * 128 + ((chunk ^ (row & 7)) << 4));
}

// ---------------------------------------------------------------------------
// Precompute kernels
// ---------------------------------------------------------------------------
__global__ void split_inputs_kernel(const float* __restrict__ src) {
    int n4 = N_ROWS * DDIM / 4;
    for (int i = blockIdx.x * blockDim.x + threadIdx.x; i < n4; i += gridDim.x * blockDim.x) {
        float4 v = reinterpret_cast<const float4*>(src)[i];
        __nv_bfloat16 h[4] = {__float2bfloat16_rn(v.x), __float2bfloat16_rn(v.y),
                              __float2bfloat16_rn(v.z), __float2bfloat16_rn(v.w)};
        reinterpret_cast<uint2*>(g_Ah)[i] = *reinterpret_cast<uint2*>(h);
    }
}
__global__ void split_codebook_kernel(const float* __restrict__ src) {
    int n4 = KCODES * DDIM / 4;
    for (int i = blockIdx.x * blockDim.x + threadIdx.x; i < n4; i += gridDim.x * blockDim.x) {
        float4 v = reinterpret_cast<const float4*>(src)[i];
        __nv_bfloat16 h[4] = {__float2bfloat16_rn(v.x), __float2bfloat16_rn(v.y),
                              __float2bfloat16_rn(v.z), __float2bfloat16_rn(v.w)};
        reinterpret_cast<uint2*>(g_Ch)[i] = *reinterpret_cast<uint2*>(h);
    }
}
__global__ void cnorm_kernel(const float* __restrict__ cb) {
    int k = blockIdx.x;
    const float4* row = reinterpret_cast<const float4*>(cb + (size_t)k * DDIM);
    float s = 0.f;
    for (int i = threadIdx.x; i < DDIM / 4; i += 128) {
        float4 v = row[i];
        s += v.x * v.x + v.y * v.y + v.z * v.z + v.w * v.w;
    }
#pragma unroll
    for (int o = 16; o > 0; o >>= 1) s += __shfl_xor_sync(0xffffffffu, s, o);
    __shared__ float ws[4];
    if ((threadIdx.x & 31) == 0) ws[threadIdx.x >> 5] = s;
    __syncthreads();
    if (threadIdx.x == 0) g_cnorm[k] = ws[0] + ws[1] + ws[2] + ws[3];
}

// ---------------------------------------------------------------------------
// Coarse pass: bf16 GEMM (xh . ch) + per-thread top-2 per row-slot.
// Grid 256 CTAs x 256 threads, 2 CTAs/SM.
// 8 warps in a 4x2 grid; warp tile 32 rows x 64 codes (acc[2][8][4] = 64 regs).
// ---------------------------------------------------------------------------
__device__ __forceinline__ void issue_stage(uint32_t aBase, uint32_t bBase,
                                            int r0, int c0, int ks, int tid) {
#pragma unroll
    for (int i = 0; i < 4; ++i) {
        int idx = tid + i * 256;        // 0..1023
        int row = idx >> 3, ch = idx & 7;
        cp_async16(aBase + sw_off(row, ch),
                   g_Ah + (size_t)(r0 + row) * DDIM + ks + ch * 8);
    }
#pragma unroll
    for (int i = 0; i < 4; ++i) {
        int idx = tid + i * 256;
        int row = idx >> 3, ch = idx & 7;
        cp_async16(bBase + sw_off(row, ch),
                   g_Ch + (size_t)(c0 + row) * DDIM + ks + ch * 8);
    }
    CP_COMMIT();
}

__global__ void __launch_bounds__(256, 2)
vq_coarse_kernel() {
    extern __shared__ char smem[];
    const uint32_t sb = smem_to_u32(smem);
    const int tid  = threadIdx.x;
    const int lane = tid & 31;
    const int warp = tid >> 5;
    const int wm = warp >> 1;          // 0..3 (32 rows each)
    const int wn = warp & 1;           // 0..1 (64 codes each)
    const int r0 = blockIdx.x * MT;

    const int sub  = lane >> 3;
    const int lrow = (sub & 1) * 8 + (lane & 7);
    const int lchk = sub >> 1;

    float acc[2][8][4];
#pragma unroll
    for (int mi = 0; mi < 2; ++mi)
#pragma unroll
        for (int n8 = 0; n8 < 8; ++n8)
#pragma unroll
            for (int e = 0; e < 4; ++e) acc[mi][n8][e] = 0.f;

    // per row-slot top-2 (4 slots: mi*2 + rowhalf)
    float v0[4], v1[4];
    int   i0[4], i1[4];
#pragma unroll
    for (int s = 0; s < 4; ++s) { v0[s] = v1[s] = 3.0e38f; i0[s] = i1[s] = 0x7fffffff; }

    issue_stage(sb, sb + 16384, r0, 0, 0, tid);
    issue_stage(sb + STAGE_BYTES, sb + STAGE_BYTES + 16384, r0, 0, 64, tid);

#pragma unroll 1
    for (int t = 0; t < TOTAL_TILES; ++t) {
        const int chunk = t >> 3;
        const int kt = t & 7;

        if (t == TOTAL_TILES - 1) { CP_WAIT(0); } else { CP_WAIT(1); }
        __syncthreads();

        if (t + 2 < TOTAL_TILES) {
            const int t2 = t + 2;
            const int s2 = t2 % NSTG;
            issue_stage(sb + s2 * STAGE_BYTES, sb + s2 * STAGE_BYTES + 16384,
                        r0, (t2 >> 3) * NT, (t2 & 7) * BK, tid);
        }

        const uint32_t aBase = sb + (t % NSTG) * STAGE_BYTES;
        const uint32_t bBase = aBase + 16384;
#pragma unroll
        for (int kk = 0; kk < 4; ++kk) {
            uint32_t a[2][4];
#pragma unroll
            for (int mi = 0; mi < 2; ++mi)
                ldsm_x4(a[mi][0], a[mi][1], a[mi][2], a[mi][3],
                        aBase + sw_off(wm * 32 + mi * 16 + lrow, kk * 2 + lchk));
            uint32_t bfr[4][4];
#pragma unroll
            for (int ni = 0; ni < 4; ++ni)
                ldsm_x4(bfr[ni][0], bfr[ni][1], bfr[ni][2], bfr[ni][3],
                        bBase + sw_off(wn * 64 + ni * 16 + lrow, kk * 2 + lchk));
#pragma unroll
            for (int mi = 0; mi < 2; ++mi)
#pragma unroll
                for (int n8 = 0; n8 < 8; ++n8)
                    mma16816(acc[mi][n8], a[mi],
                             bfr[n8 >> 1][n8 & 1], bfr[n8 >> 1][(n8 & 1) + 2]);
        }

        if (kt == KT_PER_CHUNK - 1) {
            const int c0 = chunk * NT;
#pragma unroll
            for (int n8 = 0; n8 < 8; ++n8) {
                const int col = c0 + wn * 64 + n8 * 8 + 2 * (lane & 3);
                const float cn0 = __ldg(&g_cnorm[col]);
                const float cn1 = __ldg(&g_cnorm[col + 1]);
#pragma unroll
                for (int mi = 0; mi < 2; ++mi) {
#pragma unroll
                    for (int e = 0; e < 4; ++e) {
                        const int slot = mi * 2 + (e >> 1);
                        const float cn = (e & 1) ? cn1 : cn0;
                        const int   cx = col + (e & 1);
                        float d = fmaf(-2.f, acc[mi][n8][e], cn);
                        if (d < v1[slot]) {
                            if (d < v0[slot]) {
                                v1[slot] = v0[slot]; i1[slot] = i0[slot];
                                v0[slot] = d;        i0[slot] = cx;
                            } else { v1[slot] = d; i1[slot] = cx; }
                        }
                        acc[mi][n8][e] = 0.f;
                    }
                }
            }
        }
    }

    // Merge 8 threads x 2 entries per row -> global top-4 per row
    __syncthreads();
    float* mv = reinterpret_cast<float*>(smem);            // [128][16]
    int*   md = reinterpret_cast<int*>(smem + 8192);       // [128][16]
#pragma unroll
    for (int slot = 0; slot < 4; ++slot) {
        const int mi = slot >> 1, rh = slot & 1;
        const int row = wm * 32 + mi * 16 + rh * 8 + (lane >> 2);
        const int col = wn * 8 + (lane & 3) * 2;
        mv[row * 16 + col]     = v0[slot];
        md[row * 16 + col]     = i0[slot];
        mv[row * 16 + col + 1] = v1[slot];
        md[row * 16 + col + 1] = i1[slot];
    }
    __syncthreads();
    if (tid < MT) {
        float tv[4] = {3.0e38f, 3.0e38f, 3.0e38f, 3.0e38f};
        int   ti[4] = {0x7fffffff, 0x7fffffff, 0x7fffffff, 0x7fffffff};
#pragma unroll 4
        for (int e = 0; e < 16; ++e) {
            float v = mv[tid * 16 + e];
            int   d = md[tid * 16 + e];
            if (v < tv[3] || (v == tv[3] && d < ti[3])) {
                tv[3] = v; ti[3] = d;
#pragma unroll
                for (int j = 3; j >= 1; --j) {
                    if (tv[j] < tv[j-1] || (tv[j] == tv[j-1] && ti[j] < ti[j-1])) {
                        float fv = tv[j]; tv[j] = tv[j-1]; tv[j-1] = fv;
                        int   fi = ti[j]; ti[j] = ti[j-1]; ti[j-1] = fi;
                    }
                }
            }
        }
#pragma unroll
        for (int j = 0; j < 4; ++j) g_cand[(r0 + tid) * 4 + j] = ti[j];
    }
}

// ---------------------------------------------------------------------------
// Exact refine + gather. One warp per row; 4 candidates, fp32 dots.
// ---------------------------------------------------------------------------
__global__ void __launch_bounds__(256)
refine_kernel(const float* __restrict__ cb, const float* __restrict__ x,
              float* __restrict__ out) {
    const int n = blockIdx.x * 8 + (threadIdx.x >> 5);
    const int lane = threadIdx.x & 31;

    float xr[16];
#pragma unroll
    for (int j = 0; j < 16; ++j) xr[j] = x[(size_t)n * DDIM + j * 32 + lane];

    float bv = 3.0e38f;
    int   bi = 0x7fffffff;
#pragma unroll
    for (int c = 0; c < 4; ++c) {
        const int k = g_cand[n * 4 + c];
        const float* crow = cb + (size_t)k * DDIM;
        float s = 0.f;
#pragma unroll
        for (int j = 0; j < 16; ++j) s = fmaf(xr[j], __ldg(crow + j * 32 + lane), s);
#pragma unroll
        for (int o = 16; o > 0; o >>= 1) s += __shfl_xor_sync(0xffffffffu, s, o);
        float d2 = fmaf(-2.f, s, __ldg(&g_cnorm[k]));
        if (d2 < bv || (d2 == bv && k < bi)) { bv = d2; bi = k; }
    }

    const float* q = cb + (size_t)bi * DDIM;
#pragma unroll
    for (int j = 0; j < 16; ++j) {
        float qv = __ldg(q + j * 32 + lane);
        float xv = xr[j];
        out[(size_t)n * DDIM + j * 32 + lane] = (qv - xv) + xv;
    }
}

// ---------------------------------------------------------------------------
extern "C" void kernel_launch(void* const* d_in, const int* in_sizes, int n_in,
                              void* d_out, int out_size) {
    const float* inputs   = (const float*)d_in[0];
    const float* codebook = (const float*)d_in[1];
    float* out = (float*)d_out;

    cudaFuncSetAttribute(vq_coarse_kernel, cudaFuncAttributeMaxDynamicSharedMemorySize,
                         SMEM_TOTAL);

    split_inputs_kernel<<<4096, 256>>>(inputs);
    split_codebook_kernel<<<512, 256>>>(codebook);
    cnorm_kernel<<<KCODES, 128>>>(codebook);
    vq_coarse_kernel<<<N_ROWS / MT, 256, SMEM_TOTAL>>>();
    refine_kernel<<<N_ROWS / 8, 256>>>(codebook, inputs, out);
}